// round 11
// baseline (speedup 1.0000x reference)
#include <cuda_runtime.h>
#include <math.h>

// Problem constants (fixed by setup_inputs)
#define N_NODES 4096
#define IN_DIM  512
#define H_DIM   256
#define OUTD    64
#define MAXDEG  192
#define EPSV    1e-8f
#define A_SCAD  3.7f
#define PROP_STEP 4
#define SEL_BLOCKS 148        // <= SM count: all blocks co-resident -> spin barrier is safe

static const float LAMF = (float)(1.0 / 0.9 - 1.0);   // 1/LAM_HAT - 1

// ---------------- device scratch (static, no allocation) ----------------
__device__ float g_dsq[N_NODES];
__device__ int   g_cnt[N_NODES];
__device__ int   g_cols[N_NODES * MAXDEG];
__device__ float g_y   [N_NODES * MAXDEG];
__device__ float g_Fu  [N_NODES * OUTD];
__device__ float g_F0  [N_NODES * OUTD];
__device__ float g_FA  [N_NODES * OUTD];
__device__ float g_FB  [N_NODES * OUTD];
__device__ float g_H   [N_NODES * H_DIM];
__device__ unsigned g_hist0[256];
__device__ unsigned g_selh[3][512];    // per-pass buffers (no inter-pass zeroing races)
__device__ float    g_lamc;
__device__ int      g_M;
__device__ int          g_bar_count;
__device__ volatile int g_bar_phase;

// ---------------- grid barrier (requires all blocks co-resident) ------------
__device__ __forceinline__ void grid_bar(int nb) {
    __syncthreads();
    if (threadIdx.x == 0) {
        __threadfence();
        int gen = g_bar_phase;
        if (atomicAdd(&g_bar_count, 1) == nb - 1) {
            g_bar_count = 0;
            __threadfence();
            g_bar_phase = gen + 1;
        } else {
            while (g_bar_phase == gen) __nanosleep(64);
        }
        __threadfence();
    }
    __syncthreads();
}

// ---------------- reset ----------------
__global__ void reset_kernel() {
    int i = threadIdx.x;
    if (i == 0) { g_M = 0; g_bar_count = 0; g_bar_phase = 0; }
    if (i < 256) g_hist0[i] = 0;
    for (int j = i; j < 3 * 512; j += blockDim.x) ((unsigned*)g_selh)[j] = 0;
}

// ---------------- build padded adjacency (deterministic, column-sorted) ----
__global__ __launch_bounds__(256) void build_kernel(const float* __restrict__ A) {
    __shared__ unsigned char sbit[N_NODES];
    __shared__ int scnt[256];
    int row = blockIdx.x, tid = threadIdx.x;
    const float* Arow = A + (size_t)row * N_NODES;
    for (int i = tid; i < N_NODES; i += 256) sbit[i] = (Arow[i] != 0.0f);
    __syncthreads();
    int c0 = tid * 16;
    int cnt = 0;
#pragma unroll
    for (int c = 0; c < 16; c++) cnt += sbit[c0 + c];
    scnt[tid] = cnt;
    __syncthreads();
    for (int off = 1; off < 256; off <<= 1) {
        int v = (tid >= off) ? scnt[tid - off] : 0;
        __syncthreads();
        scnt[tid] += v;
        __syncthreads();
    }
    int base  = scnt[tid] - cnt;
    int total = scnt[255];
    int pos = base;
    for (int c = 0; c < 16; c++)
        if (sbit[c0 + c] && pos < MAXDEG) g_cols[row * MAXDEG + (pos++)] = c0 + c;
    int t = min(total, MAXDEG);
    // one-time +inf padding of g_y (never rewritten; sorts past all real y)
    for (int e = t + tid; e < MAXDEG; e += 256)
        g_y[row * MAXDEG + e] = __int_as_float(0x7f800000);
    if (tid == 0) {
        g_cnt[row] = t;
        g_dsq[row] = sqrtf((float)(total + 1));   // D = deg + self-loop
        atomicAdd(&g_M, t);
    }
}

// ---------------- software-pipelined fp32 GEMM1: H = relu(X @ W1 + b1) ------
__global__ __launch_bounds__(256) void gemm1_kernel(const float* __restrict__ A,
                                                    const float* __restrict__ B,
                                                    const float* __restrict__ bias,
                                                    float* __restrict__ C) {
    const int N = H_DIM, K = IN_DIM;
    __shared__ float As[16][64];
    __shared__ float Bs[16][64];
    int tid = threadIdx.x;
    int tx = tid & 15, ty = tid >> 4;
    int row0 = blockIdx.y * 64, col0 = blockIdx.x * 64;
    int ar = tid >> 2, ak = (tid & 3) * 4;
    int bk = tid >> 4, bc = (tid & 15) * 4;
    const float* Aptr = A + (size_t)(row0 + ar) * K + ak;
    const float* Bptr = B + (size_t)bk * N + col0 + bc;

    float acc[4][4];
#pragma unroll
    for (int i = 0; i < 4; i++)
#pragma unroll
        for (int j = 0; j < 4; j++) acc[i][j] = 0.0f;

    float4 av = *(const float4*)Aptr;
    float4 bv = *(const float4*)Bptr;

    for (int k0 = 0; k0 < K; k0 += 16) {
        As[ak + 0][ar] = av.x; As[ak + 1][ar] = av.y;
        As[ak + 2][ar] = av.z; As[ak + 3][ar] = av.w;
        *(float4*)&Bs[bk][bc] = bv;
        __syncthreads();
        if (k0 + 16 < K) {
            av = *(const float4*)(Aptr + k0 + 16);
            bv = *(const float4*)(Bptr + (size_t)(k0 + 16) * N);
        }
#pragma unroll
        for (int kk = 0; kk < 16; kk++) {
            float4 a = *(float4*)&As[kk][ty * 4];
            float4 b = *(float4*)&Bs[kk][tx * 4];
            float avr[4] = {a.x, a.y, a.z, a.w};
            float bvr[4] = {b.x, b.y, b.z, b.w};
#pragma unroll
            for (int i = 0; i < 4; i++)
#pragma unroll
                for (int j = 0; j < 4; j++) acc[i][j] = fmaf(avr[i], bvr[j], acc[i][j]);
        }
        __syncthreads();
    }
#pragma unroll
    for (int i = 0; i < 4; i++) {
        int r = row0 + ty * 4 + i;
        float4 o;
        o.x = fmaxf(acc[i][0] + bias[col0 + tx * 4 + 0], 0.0f);
        o.y = fmaxf(acc[i][1] + bias[col0 + tx * 4 + 1], 0.0f);
        o.z = fmaxf(acc[i][2] + bias[col0 + tx * 4 + 2], 0.0f);
        o.w = fmaxf(acc[i][3] + bias[col0 + tx * 4 + 3], 0.0f);
        *(float4*)&C[(size_t)r * N + col0 + tx * 4] = o;
    }
}

// ------ GEMM2 fused: F0 = H @ W2 + b2 ; Fu = rownorm(F0 / dsq) --------------
// N = OUTD = 64 -> grid.x = 1: every block owns complete rows.
__global__ __launch_bounds__(256) void gemm2_fused_kernel(const float* __restrict__ A,
                                                          const float* __restrict__ B,
                                                          const float* __restrict__ bias) {
    const int N = OUTD, K = H_DIM;
    __shared__ float As[16][64];
    __shared__ float Bs[16][64];
    int tid = threadIdx.x;
    int tx = tid & 15, ty = tid >> 4;
    int row0 = blockIdx.y * 64;
    int ar = tid >> 2, ak = (tid & 3) * 4;
    int bk = tid >> 4, bc = (tid & 15) * 4;
    const float* Aptr = A + (size_t)(row0 + ar) * K + ak;
    const float* Bptr = B + (size_t)bk * N + bc;

    float acc[4][4];
#pragma unroll
    for (int i = 0; i < 4; i++)
#pragma unroll
        for (int j = 0; j < 4; j++) acc[i][j] = 0.0f;

    float4 av = *(const float4*)Aptr;
    float4 bv = *(const float4*)Bptr;

    for (int k0 = 0; k0 < K; k0 += 16) {
        As[ak + 0][ar] = av.x; As[ak + 1][ar] = av.y;
        As[ak + 2][ar] = av.z; As[ak + 3][ar] = av.w;
        *(float4*)&Bs[bk][bc] = bv;
        __syncthreads();
        if (k0 + 16 < K) {
            av = *(const float4*)(Aptr + k0 + 16);
            bv = *(const float4*)(Bptr + (size_t)(k0 + 16) * N);
        }
#pragma unroll
        for (int kk = 0; kk < 16; kk++) {
            float4 a = *(float4*)&As[kk][ty * 4];
            float4 b = *(float4*)&Bs[kk][tx * 4];
            float avr[4] = {a.x, a.y, a.z, a.w};
            float bvr[4] = {b.x, b.y, b.z, b.w};
#pragma unroll
            for (int i = 0; i < 4; i++)
#pragma unroll
                for (int j = 0; j < 4; j++) acc[i][j] = fmaf(avr[i], bvr[j], acc[i][j]);
        }
        __syncthreads();
    }
    // epilogue: F0 store + fused normalize -> Fu  (row spread over 16 lanes)
#pragma unroll
    for (int i = 0; i < 4; i++) {
        int r = row0 + ty * 4 + i;
        float4 o;
        o.x = acc[i][0] + bias[tx * 4 + 0];
        o.y = acc[i][1] + bias[tx * 4 + 1];
        o.z = acc[i][2] + bias[tx * 4 + 2];
        o.w = acc[i][3] + bias[tx * 4 + 3];
        *(float4*)&g_F0[r * OUTD + tx * 4] = o;
        float d = g_dsq[r];
        float vx = o.x / d, vy = o.y / d, vz = o.z / d, vw = o.w / d;
        float p = vx * vx + vy * vy + vz * vz + vw * vw;
#pragma unroll
        for (int off = 8; off; off >>= 1) p += __shfl_xor_sync(0xffffffffu, p, off);
        float inv = 1.0f / fmaxf(sqrtf(p), EPSV);
        float4 fo;
        fo.x = vx * inv; fo.y = vy * inv; fo.z = vz * inv; fo.w = vw * inv;
        *(float4*)&g_Fu[r * OUTD + tx * 4] = fo;
    }
}

// ---- per-edge y: float4 half-warp dot; WARP-UNIFORM trip count (no hang) ---
__global__ __launch_bounds__(256) void ycompute_kernel() {
    __shared__ unsigned hist[256];
    int row = blockIdx.x, tid = threadIdx.x;
    int lane = tid & 31, warp = tid >> 5;
    int half = lane >> 4, hl = lane & 15;       // half-warp id, lane within half
    hist[tid] = 0;
    __syncthreads();
    float4 f4 = *(const float4*)&g_Fu[row * OUTD + hl * 4];
    int cnt = g_cnt[row];
    const int* cols = g_cols + row * MAXDEG;
    float* yrow = g_y + row * MAXDEG;
    // eb is uniform across the warp -> all 32 lanes take every iteration together
    for (int eb = warp * 2; eb < cnt; eb += 16) {
        int e = eb + half;
        bool valid = (e < cnt);
        int j = cols[valid ? e : eb];
        float4 g4 = *(const float4*)&g_Fu[j * OUTD + hl * 4];
        float p = f4.x * g4.x + f4.y * g4.y + f4.z * g4.z + f4.w * g4.w;
        p += __shfl_xor_sync(0xffffffffu, p, 8);
        p += __shfl_xor_sync(0xffffffffu, p, 4);
        p += __shfl_xor_sync(0xffffffffu, p, 2);
        p += __shfl_xor_sync(0xffffffffu, p, 1);
        if (valid && hl == 0) {
            float yv = fminf(fmaxf(1.0f - p, 0.0f), 2.0f);
            yrow[e] = yv;
            atomicAdd(&hist[__float_as_uint(yv) >> 24], 1u);
        }
    }
    __syncthreads();
    if (hist[tid]) atomicAdd(&g_hist0[tid], hist[tid]);
}

// -------- fused exact radix select: init + 3 passes, grid-sync'd ------------
__global__ __launch_bounds__(256) void sel_fused_kernel(const float* __restrict__ lg0,
                                                        const float* __restrict__ rdec,
                                                        const float* __restrict__ ralpha,
                                                        int kiter) {
    __shared__ unsigned h[512];
    __shared__ unsigned sscan[256];
    __shared__ unsigned sprefix[2];
    __shared__ int      srank[2];
    int tid = threadIdx.x;
    int M = g_M;

    float g0 = expf(lg0[0]);
    float rr = 1.0f / (1.0f + expf(-rdec[0]));
    float gp = g0 * powf(rr, (float)kiter);
    float al = 1.0f / (1.0f + expf(-ralpha[0]));

    if (M <= 0) {       // uniform across all blocks: no barrier imbalance
        if (blockIdx.x == 0 && tid == 0) {
            float gd = 1.0f;
            g_lamc = al * (gp / A_SCAD) + (1.0f - al) * (gd / A_SCAD);
        }
        return;
    }

    double idx = 0.75 * (double)(M - 1);
    long k0l = (long)floor(idx);
    float frac = (float)(idx - (double)k0l);
    int R0 = (int)k0l;
    long k1l = k0l + 1; if (k1l > (long)(M - 1)) k1l = M - 1;
    int R1 = (int)k1l;

    // level-0: scan g_hist0, locate top-byte bins for both ranks (per-block)
    unsigned c = g_hist0[tid];
    sscan[tid] = c;
    __syncthreads();
    for (int off = 1; off < 256; off <<= 1) {
        unsigned v = (tid >= off) ? sscan[tid - off] : 0;
        __syncthreads();
        sscan[tid] += v;
        __syncthreads();
    }
    {
        unsigned incl = sscan[tid], excl = incl - c;
        if ((unsigned)R0 >= excl && (unsigned)R0 < incl) { sprefix[0] = (unsigned)tid << 24; srank[0] = R0 - (int)excl; }
        if ((unsigned)R1 >= excl && (unsigned)R1 < incl) { sprefix[1] = (unsigned)tid << 24; srank[1] = R1 - (int)excl; }
    }
    __syncthreads();
    unsigned p0 = sprefix[0], p1 = sprefix[1];
    int r0 = srank[0], r1 = srank[1];
    __syncthreads();

    const int SH[3] = {16, 8, 0};
    for (int p = 0; p < 3; p++) {
        int sh = SH[p];
        unsigned hm = (sh == 16) ? 0xFF000000u : (sh == 8) ? 0xFFFF0000u : 0xFFFFFF00u;
        h[tid] = 0; h[tid + 256] = 0;
        __syncthreads();
        const int T = N_NODES * MAXDEG;
        for (int s = blockIdx.x * 256 + tid; s < T; s += SEL_BLOCKS * 256) {
            unsigned u = __float_as_uint(g_y[s]);
            unsigned b = (u >> sh) & 0xFFu;
            if ((u & hm) == p0) atomicAdd(&h[b], 1u);
            if ((u & hm) == p1) atomicAdd(&h[256 + b], 1u);
        }
        __syncthreads();
        if (h[tid])       atomicAdd(&g_selh[p][tid], h[tid]);
        if (h[tid + 256]) atomicAdd(&g_selh[p][tid + 256], h[tid + 256]);
        grid_bar(SEL_BLOCKS);
        // each block redundantly scans the completed pass histogram
        for (int t = 0; t < 2; t++) {
            unsigned cc = g_selh[p][t * 256 + tid];
            sscan[tid] = cc;
            __syncthreads();
            for (int off = 1; off < 256; off <<= 1) {
                unsigned v = (tid >= off) ? sscan[tid - off] : 0;
                __syncthreads();
                sscan[tid] += v;
                __syncthreads();
            }
            unsigned incl = sscan[tid], excl = incl - cc;
            int r = (t == 0) ? r0 : r1;
            if ((unsigned)r >= excl && (unsigned)r < incl) {
                sprefix[t] = ((t == 0) ? p0 : p1) | ((unsigned)tid << sh);
                srank[t] = r - (int)excl;
            }
            __syncthreads();
        }
        p0 = sprefix[0]; p1 = sprefix[1];
        r0 = srank[0];   r1 = srank[1];
        __syncthreads();
    }
    if (blockIdx.x == 0 && tid == 0) {
        float v0 = __uint_as_float(p0);
        float v1 = __uint_as_float(p1);
        float gd = fmaxf(v0 * (1.0f - frac) + v1 * frac, EPSV);
        g_lamc = al * (gp / A_SCAD) + (1.0f - al) * (gd / A_SCAD);
    }
}

// ------- SCAD weights + sparse propagation (+fused normalize, hist zeroing) --
__global__ __launch_bounds__(64) void propagate_kernel(const float* __restrict__ Fin,
                                                       float* __restrict__ Fout,
                                                       float lam, int write_fu) {
    __shared__ float ssc[MAXDEG];
    __shared__ int   sj[MAXDEG];
    __shared__ float red[2];
    int row = blockIdx.x, t = threadIdx.x;

    // zero histograms for next iteration (rows 0..27 cover 256 + 1536 words)
    {
        int gid = row * 64 + t;
        if (gid < 256) g_hist0[gid] = 0;
        else if (gid < 256 + 3 * 512) ((unsigned*)g_selh)[gid - 256] = 0;
    }

    int cnt = g_cnt[row];
    float lamc = g_lamc;
    float di = g_dsq[row];
    float ps = 0.0f;
    for (int e = t; e < cnt; e += 64) {
        float y  = g_y[row * MAXDEG + e];
        float ys = fmaxf(y, EPSV);
        float wm = (A_SCAD * lamc - y) / ((A_SCAD - 1.0f) * ys);
        float w  = (y <= lamc) ? 1.0f : ((y <= A_SCAD * lamc) ? wm : 0.0f);
        int j = g_cols[row * MAXDEG + e];
        ssc[e] = w / (di * g_dsq[j]);
        sj[e]  = j;
        ps += w;
    }
#pragma unroll
    for (int o = 16; o; o >>= 1) ps += __shfl_xor_sync(0xffffffffu, ps, o);
    if ((t & 31) == 0) red[t >> 5] = ps;
    __syncthreads();
    float S = red[0] + red[1];
    float Q = S / (float)(cnt + 1) + lam;
    // 4-accumulator gather (MLP)
    float a0 = 0.0f, a1 = 0.0f, a2 = 0.0f, a3 = 0.0f;
    int e = 0;
    for (; e + 4 <= cnt; e += 4) {
        a0 = fmaf(ssc[e + 0], Fin[sj[e + 0] * OUTD + t], a0);
        a1 = fmaf(ssc[e + 1], Fin[sj[e + 1] * OUTD + t], a1);
        a2 = fmaf(ssc[e + 2], Fin[sj[e + 2] * OUTD + t], a2);
        a3 = fmaf(ssc[e + 3], Fin[sj[e + 3] * OUTD + t], a3);
    }
    for (; e < cnt; e++) a0 = fmaf(ssc[e], Fin[sj[e] * OUTD + t], a0);
    float acc = (a0 + a1) + (a2 + a3);
    float f0 = g_F0[row * OUTD + t];
    float outv = acc / Q + lam * f0 / Q;
    Fout[row * OUTD + t] = outv;

    if (write_fu) {
        float v = outv / di;
        float s2 = v * v;
#pragma unroll
        for (int o = 16; o; o >>= 1) s2 += __shfl_xor_sync(0xffffffffu, s2, o);
        __shared__ float red2[2];
        if ((t & 31) == 0) red2[t >> 5] = s2;
        __syncthreads();
        float nrm = sqrtf(red2[0] + red2[1]);
        g_Fu[row * OUTD + t] = v / fmaxf(nrm, EPSV);
    }
}

// ---------------- host launcher ---------------------------------------------
extern "C" void kernel_launch(void* const* d_in, const int* in_sizes, int n_in,
                              void* d_out, int out_size) {
    const float* A      = (const float*)d_in[0];
    const float* X      = (const float*)d_in[1];
    const float* W1     = (const float*)d_in[2];
    const float* b1     = (const float*)d_in[3];
    const float* W2     = (const float*)d_in[4];
    const float* b2     = (const float*)d_in[5];
    const float* lg0    = (const float*)d_in[6];
    const float* rdec   = (const float*)d_in[7];
    const float* ralpha = (const float*)d_in[8];
    float* out = (float*)d_out;

    // DEVICE addresses of the __device__ buffers (host shadow symbols are NOT valid!)
    float *pH, *pF0, *pFA, *pFB;
    cudaGetSymbolAddress((void**)&pH,  g_H);
    cudaGetSymbolAddress((void**)&pF0, g_F0);
    cudaGetSymbolAddress((void**)&pFA, g_FA);
    cudaGetSymbolAddress((void**)&pFB, g_FB);

    reset_kernel<<<1, 1024>>>();
    build_kernel<<<N_NODES, 256>>>(A);

    gemm1_kernel<<<dim3(H_DIM / 64, N_NODES / 64), 256>>>(X, W1, b1, pH);
    gemm2_fused_kernel<<<dim3(1, N_NODES / 64), 256>>>(pH, W2, b2);

    for (int k = 0; k < PROP_STEP; k++) {
        const float* Fin = (k == 0) ? pF0 : ((k & 1) ? pFA : pFB);
        float* Fout = (k == PROP_STEP - 1) ? out : ((k & 1) ? pFB : pFA);

        ycompute_kernel<<<N_NODES, 256>>>();
        sel_fused_kernel<<<SEL_BLOCKS, 256>>>(lg0, rdec, ralpha, k);
        propagate_kernel<<<N_NODES, 64>>>(Fin, Fout, LAMF, (k < PROP_STEP - 1) ? 1 : 0);
    }
}

// round 12
// speedup vs baseline: 1.4748x; 1.4748x over previous
#include <cuda_runtime.h>
#include <math.h>

// Problem constants (fixed by setup_inputs)
#define N_NODES 4096
#define IN_DIM  512
#define H_DIM   256
#define OUTD    64
#define MAXDEG  192
#define EPSV    1e-8f
#define A_SCAD  3.7f
#define PROP_STEP 4
#define SEL_BLOCKS 148        // <= SM count: all blocks co-resident -> spin barrier is safe

static const float LAMF = (float)(1.0 / 0.9 - 1.0);   // 1/LAM_HAT - 1

// ---------------- device scratch (static, no allocation) ----------------
__device__ float g_dsq [N_NODES];
__device__ float g_rdsq[N_NODES];
__device__ int   g_cnt[N_NODES];
__device__ int   g_cols[N_NODES * MAXDEG];
__device__ float g_y   [N_NODES * MAXDEG];
__device__ float g_Fu  [N_NODES * OUTD];
__device__ float g_F0  [N_NODES * OUTD];
__device__ float g_FA  [N_NODES * OUTD];
__device__ float g_FB  [N_NODES * OUTD];
__device__ float g_H   [N_NODES * H_DIM];
__device__ unsigned g_hist0[256];
__device__ unsigned g_sel12[2][2][4096];   // [pass][rank][bin] per-pass buffers
__device__ float    g_lamc;
__device__ int      g_M;
__device__ int          g_bar_count;
__device__ volatile int g_bar_phase;

#define SEL12_WORDS (2 * 2 * 4096)

// ---------------- grid barrier (requires all blocks co-resident) ------------
__device__ __forceinline__ void grid_bar(int nb) {
    __syncthreads();
    if (threadIdx.x == 0) {
        __threadfence();
        int gen = g_bar_phase;
        if (atomicAdd(&g_bar_count, 1) == nb - 1) {
            g_bar_count = 0;
            __threadfence();
            g_bar_phase = gen + 1;
        } else {
            while (g_bar_phase == gen) __nanosleep(64);
        }
        __threadfence();
    }
    __syncthreads();
}

// ---------------- reset ----------------
__global__ void reset_kernel() {
    int i = threadIdx.x;
    if (i == 0) { g_M = 0; g_bar_count = 0; g_bar_phase = 0; }
    if (i < 256) g_hist0[i] = 0;
    for (int j = i; j < SEL12_WORDS; j += blockDim.x) ((unsigned*)g_sel12)[j] = 0;
}

// ---------------- build padded adjacency (deterministic, column-sorted) ----
__global__ __launch_bounds__(256) void build_kernel(const float* __restrict__ A) {
    __shared__ unsigned char sbit[N_NODES];
    __shared__ int scnt[256];
    int row = blockIdx.x, tid = threadIdx.x;
    const float* Arow = A + (size_t)row * N_NODES;
    for (int i = tid; i < N_NODES; i += 256) sbit[i] = (Arow[i] != 0.0f);
    __syncthreads();
    int c0 = tid * 16;
    int cnt = 0;
#pragma unroll
    for (int c = 0; c < 16; c++) cnt += sbit[c0 + c];
    scnt[tid] = cnt;
    __syncthreads();
    for (int off = 1; off < 256; off <<= 1) {
        int v = (tid >= off) ? scnt[tid - off] : 0;
        __syncthreads();
        scnt[tid] += v;
        __syncthreads();
    }
    int base  = scnt[tid] - cnt;
    int total = scnt[255];
    int pos = base;
    for (int c = 0; c < 16; c++)
        if (sbit[c0 + c] && pos < MAXDEG) g_cols[row * MAXDEG + (pos++)] = c0 + c;
    int t = min(total, MAXDEG);
    // one-time +inf padding of g_y (never rewritten; sorts past all real y)
    for (int e = t + tid; e < MAXDEG; e += 256)
        g_y[row * MAXDEG + e] = __int_as_float(0x7f800000);
    if (tid == 0) {
        g_cnt[row] = t;
        float d = sqrtf((float)(total + 1));   // D = deg + self-loop
        g_dsq[row]  = d;
        g_rdsq[row] = 1.0f / d;
        atomicAdd(&g_M, t);
    }
}

// ---------------- software-pipelined fp32 GEMM1: H = relu(X @ W1 + b1) ------
__global__ __launch_bounds__(256) void gemm1_kernel(const float* __restrict__ A,
                                                    const float* __restrict__ B,
                                                    const float* __restrict__ bias,
                                                    float* __restrict__ C) {
    const int N = H_DIM, K = IN_DIM;
    __shared__ float As[16][64];
    __shared__ float Bs[16][64];
    int tid = threadIdx.x;
    int tx = tid & 15, ty = tid >> 4;
    int row0 = blockIdx.y * 64, col0 = blockIdx.x * 64;
    int ar = tid >> 2, ak = (tid & 3) * 4;
    int bk = tid >> 4, bc = (tid & 15) * 4;
    const float* Aptr = A + (size_t)(row0 + ar) * K + ak;
    const float* Bptr = B + (size_t)bk * N + col0 + bc;

    float acc[4][4];
#pragma unroll
    for (int i = 0; i < 4; i++)
#pragma unroll
        for (int j = 0; j < 4; j++) acc[i][j] = 0.0f;

    float4 av = *(const float4*)Aptr;
    float4 bv = *(const float4*)Bptr;

    for (int k0 = 0; k0 < K; k0 += 16) {
        As[ak + 0][ar] = av.x; As[ak + 1][ar] = av.y;
        As[ak + 2][ar] = av.z; As[ak + 3][ar] = av.w;
        *(float4*)&Bs[bk][bc] = bv;
        __syncthreads();
        if (k0 + 16 < K) {
            av = *(const float4*)(Aptr + k0 + 16);
            bv = *(const float4*)(Bptr + (size_t)(k0 + 16) * N);
        }
#pragma unroll
        for (int kk = 0; kk < 16; kk++) {
            float4 a = *(float4*)&As[kk][ty * 4];
            float4 b = *(float4*)&Bs[kk][tx * 4];
            float avr[4] = {a.x, a.y, a.z, a.w};
            float bvr[4] = {b.x, b.y, b.z, b.w};
#pragma unroll
            for (int i = 0; i < 4; i++)
#pragma unroll
                for (int j = 0; j < 4; j++) acc[i][j] = fmaf(avr[i], bvr[j], acc[i][j]);
        }
        __syncthreads();
    }
#pragma unroll
    for (int i = 0; i < 4; i++) {
        int r = row0 + ty * 4 + i;
        float4 o;
        o.x = fmaxf(acc[i][0] + bias[col0 + tx * 4 + 0], 0.0f);
        o.y = fmaxf(acc[i][1] + bias[col0 + tx * 4 + 1], 0.0f);
        o.z = fmaxf(acc[i][2] + bias[col0 + tx * 4 + 2], 0.0f);
        o.w = fmaxf(acc[i][3] + bias[col0 + tx * 4 + 3], 0.0f);
        *(float4*)&C[(size_t)r * N + col0 + tx * 4] = o;
    }
}

// ------ GEMM2 fused: F0 = H @ W2 + b2 ; Fu = rownorm(F0 / dsq) --------------
__global__ __launch_bounds__(256) void gemm2_fused_kernel(const float* __restrict__ A,
                                                          const float* __restrict__ B,
                                                          const float* __restrict__ bias) {
    const int N = OUTD, K = H_DIM;
    __shared__ float As[16][64];
    __shared__ float Bs[16][64];
    int tid = threadIdx.x;
    int tx = tid & 15, ty = tid >> 4;
    int row0 = blockIdx.y * 64;
    int ar = tid >> 2, ak = (tid & 3) * 4;
    int bk = tid >> 4, bc = (tid & 15) * 4;
    const float* Aptr = A + (size_t)(row0 + ar) * K + ak;
    const float* Bptr = B + (size_t)bk * N + bc;

    float acc[4][4];
#pragma unroll
    for (int i = 0; i < 4; i++)
#pragma unroll
        for (int j = 0; j < 4; j++) acc[i][j] = 0.0f;

    float4 av = *(const float4*)Aptr;
    float4 bv = *(const float4*)Bptr;

    for (int k0 = 0; k0 < K; k0 += 16) {
        As[ak + 0][ar] = av.x; As[ak + 1][ar] = av.y;
        As[ak + 2][ar] = av.z; As[ak + 3][ar] = av.w;
        *(float4*)&Bs[bk][bc] = bv;
        __syncthreads();
        if (k0 + 16 < K) {
            av = *(const float4*)(Aptr + k0 + 16);
            bv = *(const float4*)(Bptr + (size_t)(k0 + 16) * N);
        }
#pragma unroll
        for (int kk = 0; kk < 16; kk++) {
            float4 a = *(float4*)&As[kk][ty * 4];
            float4 b = *(float4*)&Bs[kk][tx * 4];
            float avr[4] = {a.x, a.y, a.z, a.w};
            float bvr[4] = {b.x, b.y, b.z, b.w};
#pragma unroll
            for (int i = 0; i < 4; i++)
#pragma unroll
                for (int j = 0; j < 4; j++) acc[i][j] = fmaf(avr[i], bvr[j], acc[i][j]);
        }
        __syncthreads();
    }
    // epilogue: F0 store + fused normalize -> Fu  (row spread over 16 lanes)
#pragma unroll
    for (int i = 0; i < 4; i++) {
        int r = row0 + ty * 4 + i;
        float4 o;
        o.x = acc[i][0] + bias[tx * 4 + 0];
        o.y = acc[i][1] + bias[tx * 4 + 1];
        o.z = acc[i][2] + bias[tx * 4 + 2];
        o.w = acc[i][3] + bias[tx * 4 + 3];
        *(float4*)&g_F0[r * OUTD + tx * 4] = o;
        float d = g_dsq[r];
        float vx = o.x / d, vy = o.y / d, vz = o.z / d, vw = o.w / d;
        float p = vx * vx + vy * vy + vz * vz + vw * vw;
#pragma unroll
        for (int off = 8; off; off >>= 1) p += __shfl_xor_sync(0xffffffffu, p, off);
        float inv = 1.0f / fmaxf(sqrtf(p), EPSV);
        float4 fo;
        fo.x = vx * inv; fo.y = vy * inv; fo.z = vz * inv; fo.w = vw * inv;
        *(float4*)&g_Fu[r * OUTD + tx * 4] = fo;
    }
}

// ---- per-edge y: float4 half-warp dot; WARP-UNIFORM trip count -------------
__global__ __launch_bounds__(256) void ycompute_kernel() {
    __shared__ unsigned hist[256];
    int row = blockIdx.x, tid = threadIdx.x;
    int lane = tid & 31, warp = tid >> 5;
    int half = lane >> 4, hl = lane & 15;       // half-warp id, lane within half
    hist[tid] = 0;
    __syncthreads();
    float4 f4 = *(const float4*)&g_Fu[row * OUTD + hl * 4];
    int cnt = g_cnt[row];
    const int* cols = g_cols + row * MAXDEG;
    float* yrow = g_y + row * MAXDEG;
    // eb is uniform across the warp -> all 32 lanes take every iteration together
    for (int eb = warp * 2; eb < cnt; eb += 16) {
        int e = eb + half;
        bool valid = (e < cnt);
        int j = cols[valid ? e : eb];
        float4 g4 = *(const float4*)&g_Fu[j * OUTD + hl * 4];
        float p = f4.x * g4.x + f4.y * g4.y + f4.z * g4.z + f4.w * g4.w;
        p += __shfl_xor_sync(0xffffffffu, p, 8);
        p += __shfl_xor_sync(0xffffffffu, p, 4);
        p += __shfl_xor_sync(0xffffffffu, p, 2);
        p += __shfl_xor_sync(0xffffffffu, p, 1);
        if (valid && hl == 0) {
            float yv = fminf(fmaxf(1.0f - p, 0.0f), 2.0f);
            yrow[e] = yv;
            atomicAdd(&hist[__float_as_uint(yv) >> 24], 1u);
        }
    }
    __syncthreads();
    if (hist[tid]) atomicAdd(&g_hist0[tid], hist[tid]);
}

// -------- fused exact select: 8-bit level-0 + TWO 12-bit passes -------------
__global__ __launch_bounds__(256) void sel_fused_kernel(const float* __restrict__ lg0,
                                                        const float* __restrict__ rdec,
                                                        const float* __restrict__ ralpha,
                                                        int kiter) {
    __shared__ unsigned h[2][4096];      // 32 KB: per-rank 4096-bin histograms
    __shared__ unsigned sscan[256];
    __shared__ unsigned sprefix[2];
    __shared__ int      srank[2];
    int tid = threadIdx.x;
    int M = g_M;

    float g0 = expf(lg0[0]);
    float rr = 1.0f / (1.0f + expf(-rdec[0]));
    float gp = g0 * powf(rr, (float)kiter);
    float al = 1.0f / (1.0f + expf(-ralpha[0]));

    if (M <= 0) {       // uniform across all blocks: no barrier imbalance
        if (blockIdx.x == 0 && tid == 0) {
            float gd = 1.0f;
            g_lamc = al * (gp / A_SCAD) + (1.0f - al) * (gd / A_SCAD);
        }
        return;
    }

    double idx = 0.75 * (double)(M - 1);
    long k0l = (long)floor(idx);
    float frac = (float)(idx - (double)k0l);
    int R0 = (int)k0l;
    long k1l = k0l + 1; if (k1l > (long)(M - 1)) k1l = M - 1;
    int R1 = (int)k1l;

    // level-0: scan g_hist0 (top byte), locate bins for both ranks (per-block)
    unsigned c = g_hist0[tid];
    sscan[tid] = c;
    __syncthreads();
    for (int off = 1; off < 256; off <<= 1) {
        unsigned v = (tid >= off) ? sscan[tid - off] : 0;
        __syncthreads();
        sscan[tid] += v;
        __syncthreads();
    }
    {
        unsigned incl = sscan[tid], excl = incl - c;
        if ((unsigned)R0 >= excl && (unsigned)R0 < incl) { sprefix[0] = (unsigned)tid << 24; srank[0] = R0 - (int)excl; }
        if ((unsigned)R1 >= excl && (unsigned)R1 < incl) { sprefix[1] = (unsigned)tid << 24; srank[1] = R1 - (int)excl; }
    }
    __syncthreads();
    unsigned p0 = sprefix[0], p1 = sprefix[1];
    int r0 = srank[0], r1 = srank[1];
    __syncthreads();

    // two 12-bit passes: bits [23:12] then [11:0]
    for (int p = 0; p < 2; p++) {
        int sh = (p == 0) ? 12 : 0;
        unsigned hm = (p == 0) ? 0xFF000000u : 0xFFFFF000u;
        for (int i = tid; i < 2 * 4096; i += 256) ((unsigned*)h)[i] = 0;
        __syncthreads();
        const int T = N_NODES * MAXDEG;
        for (int s = blockIdx.x * 256 + tid; s < T; s += SEL_BLOCKS * 256) {
            unsigned u = __float_as_uint(g_y[s]);
            unsigned b = (u >> sh) & 0xFFFu;
            if ((u & hm) == p0) atomicAdd(&h[0][b], 1u);
            if ((u & hm) == p1) atomicAdd(&h[1][b], 1u);
        }
        __syncthreads();
        for (int i = tid; i < 4096; i += 256) {
            if (h[0][i]) atomicAdd(&g_sel12[p][0][i], h[0][i]);
            if (h[1][i]) atomicAdd(&g_sel12[p][1][i], h[1][i]);
        }
        grid_bar(SEL_BLOCKS);
        // each block redundantly scans the completed 4096-bin histograms
        for (int t2 = 0; t2 < 2; t2++) {
            const unsigned* H = g_sel12[p][t2];
            int base = tid * 16;
            unsigned cnts[16];
            unsigned csum = 0;
#pragma unroll
            for (int i2 = 0; i2 < 16; i2++) { cnts[i2] = H[base + i2]; csum += cnts[i2]; }
            sscan[tid] = csum;
            __syncthreads();
            for (int off = 1; off < 256; off <<= 1) {
                unsigned v = (tid >= off) ? sscan[tid - off] : 0;
                __syncthreads();
                sscan[tid] += v;
                __syncthreads();
            }
            unsigned incl = sscan[tid], excl = incl - csum;
            int r = (t2 == 0) ? r0 : r1;
            if ((unsigned)r >= excl && (unsigned)r < incl) {
                unsigned cum = excl;
#pragma unroll
                for (int i2 = 0; i2 < 16; i2++) {
                    if (cum + cnts[i2] > (unsigned)r) {
                        sprefix[t2] = ((t2 == 0) ? p0 : p1) | ((unsigned)(base + i2) << sh);
                        srank[t2] = r - (int)cum;
                        break;
                    }
                    cum += cnts[i2];
                }
            }
            __syncthreads();
        }
        p0 = sprefix[0]; p1 = sprefix[1];
        r0 = srank[0];   r1 = srank[1];
        __syncthreads();
    }
    if (blockIdx.x == 0 && tid == 0) {
        float v0 = __uint_as_float(p0);
        float v1 = __uint_as_float(p1);
        float gd = fmaxf(v0 * (1.0f - frac) + v1 * frac, EPSV);
        g_lamc = al * (gp / A_SCAD) + (1.0f - al) * (gd / A_SCAD);
    }
}

// ------- SCAD weights + sparse propagation (+fused normalize, hist zeroing) --
__global__ __launch_bounds__(64) void propagate_kernel(const float* __restrict__ Fin,
                                                       float* __restrict__ Fout,
                                                       float lam, int write_fu) {
    __shared__ float ssc[MAXDEG];
    __shared__ int   sj[MAXDEG];
    __shared__ float red[2];
    int row = blockIdx.x, t = threadIdx.x;

    // zero histograms for next iteration (rows 0..262 cover 256 + 16384 words)
    {
        int gid = row * 64 + t;
        if (gid < 256) g_hist0[gid] = 0;
        else if (gid < 256 + SEL12_WORDS) ((unsigned*)g_sel12)[gid - 256] = 0;
    }

    int cnt = g_cnt[row];
    float lamc = g_lamc;
    float di  = g_dsq[row];
    float rdi = g_rdsq[row];
    float ps = 0.0f;
    for (int e = t; e < cnt; e += 64) {
        float y  = g_y[row * MAXDEG + e];
        float ys = fmaxf(y, EPSV);
        float wm = (A_SCAD * lamc - y) / ((A_SCAD - 1.0f) * ys);
        float w  = (y <= lamc) ? 1.0f : ((y <= A_SCAD * lamc) ? wm : 0.0f);
        int j = g_cols[row * MAXDEG + e];
        ssc[e] = w * rdi * g_rdsq[j];      // W * A_tilde at the edge (no division)
        sj[e]  = j;
        ps += w;
    }
#pragma unroll
    for (int o = 16; o; o >>= 1) ps += __shfl_xor_sync(0xffffffffu, ps, o);
    if ((t & 31) == 0) red[t >> 5] = ps;
    __syncthreads();
    float S = red[0] + red[1];
    float Q = S / (float)(cnt + 1) + lam;
    // 4-accumulator gather (MLP)
    float a0 = 0.0f, a1 = 0.0f, a2 = 0.0f, a3 = 0.0f;
    int e = 0;
    for (; e + 4 <= cnt; e += 4) {
        a0 = fmaf(ssc[e + 0], Fin[sj[e + 0] * OUTD + t], a0);
        a1 = fmaf(ssc[e + 1], Fin[sj[e + 1] * OUTD + t], a1);
        a2 = fmaf(ssc[e + 2], Fin[sj[e + 2] * OUTD + t], a2);
        a3 = fmaf(ssc[e + 3], Fin[sj[e + 3] * OUTD + t], a3);
    }
    for (; e < cnt; e++) a0 = fmaf(ssc[e], Fin[sj[e] * OUTD + t], a0);
    float acc = (a0 + a1) + (a2 + a3);
    float f0 = g_F0[row * OUTD + t];
    float outv = acc / Q + lam * f0 / Q;
    Fout[row * OUTD + t] = outv;

    if (write_fu) {
        float v = outv / di;
        float s2 = v * v;
#pragma unroll
        for (int o = 16; o; o >>= 1) s2 += __shfl_xor_sync(0xffffffffu, s2, o);
        __shared__ float red2[2];
        if ((t & 31) == 0) red2[t >> 5] = s2;
        __syncthreads();
        float nrm = sqrtf(red2[0] + red2[1]);
        g_Fu[row * OUTD + t] = v / fmaxf(nrm, EPSV);
    }
}

// ---------------- host launcher ---------------------------------------------
extern "C" void kernel_launch(void* const* d_in, const int* in_sizes, int n_in,
                              void* d_out, int out_size) {
    const float* A      = (const float*)d_in[0];
    const float* X      = (const float*)d_in[1];
    const float* W1     = (const float*)d_in[2];
    const float* b1     = (const float*)d_in[3];
    const float* W2     = (const float*)d_in[4];
    const float* b2     = (const float*)d_in[5];
    const float* lg0    = (const float*)d_in[6];
    const float* rdec   = (const float*)d_in[7];
    const float* ralpha = (const float*)d_in[8];
    float* out = (float*)d_out;

    // DEVICE addresses of the __device__ buffers (host shadow symbols are NOT valid!)
    float *pH, *pF0, *pFA, *pFB;
    cudaGetSymbolAddress((void**)&pH,  g_H);
    cudaGetSymbolAddress((void**)&pF0, g_F0);
    cudaGetSymbolAddress((void**)&pFA, g_FA);
    cudaGetSymbolAddress((void**)&pFB, g_FB);

    reset_kernel<<<1, 1024>>>();
    build_kernel<<<N_NODES, 256>>>(A);

    gemm1_kernel<<<dim3(H_DIM / 64, N_NODES / 64), 256>>>(X, W1, b1, pH);
    gemm2_fused_kernel<<<dim3(1, N_NODES / 64), 256>>>(pH, W2, b2);

    for (int k = 0; k < PROP_STEP; k++) {
        const float* Fin = (k == 0) ? pF0 : ((k & 1) ? pFA : pFB);
        float* Fout = (k == PROP_STEP - 1) ? out : ((k & 1) ? pFB : pFA);

        ycompute_kernel<<<N_NODES, 256>>>();
        sel_fused_kernel<<<SEL_BLOCKS, 256>>>(lg0, rdec, ralpha, k);
        propagate_kernel<<<N_NODES, 64>>>(Fin, Fout, LAMF, (k < PROP_STEP - 1) ? 1 : 0);
    }
}

// round 13
// speedup vs baseline: 1.5323x; 1.0389x over previous
#include <cuda_runtime.h>
#include <math.h>

// Problem constants (fixed by setup_inputs)
#define N_NODES 4096
#define IN_DIM  512
#define H_DIM   256
#define OUTD    64
#define MAXDEG  192
#define EPSV    1e-8f
#define A_SCAD  3.7f
#define PROP_STEP 4
#define SEL_BLOCKS 148        // <= SM count: all blocks co-resident -> spin barrier is safe

static const float LAMF = (float)(1.0 / 0.9 - 1.0);   // 1/LAM_HAT - 1

// ---------------- device scratch (static, no allocation) ----------------
__device__ float g_dsq [N_NODES];
__device__ float g_rdsq[N_NODES];
__device__ int   g_cnt[N_NODES];
__device__ int   g_cols[N_NODES * MAXDEG];
__device__ float g_y   [N_NODES * MAXDEG];
__device__ float g_Fu  [N_NODES * OUTD];
__device__ float g_F0  [N_NODES * OUTD];
__device__ float g_FA  [N_NODES * OUTD];
__device__ float g_FB  [N_NODES * OUTD];
__device__ float g_H   [N_NODES * H_DIM];
__device__ unsigned g_hist0[256];
__device__ unsigned g_sel12[2][2][4096];   // [pass][rank][bin] per-pass buffers
__device__ float    g_lamc;
__device__ int      g_M;
__device__ int          g_bar_count;
__device__ volatile int g_bar_phase;

#define SEL12_WORDS (2 * 2 * 4096)

// ---------------- stream fork resources (created at load, never in capture) --
static cudaStream_t g_s2;
static cudaEvent_t  g_evFork, g_evJoin;
namespace {
struct StreamInit {
    StreamInit() {
        cudaStreamCreateWithFlags(&g_s2, cudaStreamNonBlocking);
        cudaEventCreateWithFlags(&g_evFork, cudaEventDisableTiming);
        cudaEventCreateWithFlags(&g_evJoin, cudaEventDisableTiming);
    }
};
StreamInit g_stream_init;
}

// ---------------- grid barrier (requires all blocks co-resident) ------------
__device__ __forceinline__ void grid_bar(int nb) {
    __syncthreads();
    if (threadIdx.x == 0) {
        __threadfence();
        int gen = g_bar_phase;
        if (atomicAdd(&g_bar_count, 1) == nb - 1) {
            g_bar_count = 0;
            __threadfence();
            g_bar_phase = gen + 1;
        } else {
            while (g_bar_phase == gen) __nanosleep(64);
        }
        __threadfence();
    }
    __syncthreads();
}

// ---------------- reset ----------------
__global__ void reset_kernel() {
    int i = threadIdx.x;
    if (i == 0) { g_M = 0; g_bar_count = 0; g_bar_phase = 0; }
    if (i < 256) g_hist0[i] = 0;
    for (int j = i; j < SEL12_WORDS; j += blockDim.x) ((unsigned*)g_sel12)[j] = 0;
}

// ---------------- build padded adjacency (deterministic, column-sorted) ----
__global__ __launch_bounds__(256) void build_kernel(const float* __restrict__ A) {
    __shared__ unsigned char sbit[N_NODES];
    __shared__ int scnt[256];
    int row = blockIdx.x, tid = threadIdx.x;
    const float* Arow = A + (size_t)row * N_NODES;
    for (int i = tid; i < N_NODES; i += 256) sbit[i] = (Arow[i] != 0.0f);
    __syncthreads();
    int c0 = tid * 16;
    int cnt = 0;
#pragma unroll
    for (int c = 0; c < 16; c++) cnt += sbit[c0 + c];
    scnt[tid] = cnt;
    __syncthreads();
    for (int off = 1; off < 256; off <<= 1) {
        int v = (tid >= off) ? scnt[tid - off] : 0;
        __syncthreads();
        scnt[tid] += v;
        __syncthreads();
    }
    int base  = scnt[tid] - cnt;
    int total = scnt[255];
    int pos = base;
    for (int c = 0; c < 16; c++)
        if (sbit[c0 + c] && pos < MAXDEG) g_cols[row * MAXDEG + (pos++)] = c0 + c;
    int t = min(total, MAXDEG);
    // one-time +inf padding of g_y (never rewritten; sorts past all real y)
    for (int e = t + tid; e < MAXDEG; e += 256)
        g_y[row * MAXDEG + e] = __int_as_float(0x7f800000);
    if (tid == 0) {
        g_cnt[row] = t;
        float d = sqrtf((float)(total + 1));   // D = deg + self-loop
        g_dsq[row]  = d;
        g_rdsq[row] = 1.0f / d;
        atomicAdd(&g_M, t);
    }
}

// ---- GEMM1: H = relu(X @ W1 + b1). 128x64 tile, 8x4 acc, balanced wave -----
__global__ __launch_bounds__(256) void gemm1_kernel(const float* __restrict__ A,
                                                    const float* __restrict__ B,
                                                    const float* __restrict__ bias,
                                                    float* __restrict__ C) {
    const int N = H_DIM, K = IN_DIM;
    __shared__ float As[16][128];
    __shared__ float Bs[16][64];
    int tid = threadIdx.x;
    int tx = tid & 15, ty = tid >> 4;
    int row0 = blockIdx.y * 128, col0 = blockIdx.x * 64;
    int ar = tid >> 1, ak = (tid & 1) * 8;
    int bk = tid >> 4, bc = (tid & 15) * 4;
    const float* Aptr = A + (size_t)(row0 + ar) * K + ak;
    const float* Bptr = B + (size_t)bk * N + col0 + bc;

    float acc[8][4];
#pragma unroll
    for (int i = 0; i < 8; i++)
#pragma unroll
        for (int j = 0; j < 4; j++) acc[i][j] = 0.0f;

    float4 av0 = *(const float4*)Aptr;
    float4 av1 = *(const float4*)(Aptr + 4);
    float4 bv  = *(const float4*)Bptr;

    for (int k0 = 0; k0 < K; k0 += 16) {
        As[ak + 0][ar] = av0.x; As[ak + 1][ar] = av0.y;
        As[ak + 2][ar] = av0.z; As[ak + 3][ar] = av0.w;
        As[ak + 4][ar] = av1.x; As[ak + 5][ar] = av1.y;
        As[ak + 6][ar] = av1.z; As[ak + 7][ar] = av1.w;
        *(float4*)&Bs[bk][bc] = bv;
        __syncthreads();
        if (k0 + 16 < K) {
            av0 = *(const float4*)(Aptr + k0 + 16);
            av1 = *(const float4*)(Aptr + k0 + 20);
            bv  = *(const float4*)(Bptr + (size_t)(k0 + 16) * N);
        }
#pragma unroll
        for (int kk = 0; kk < 16; kk++) {
            float4 a0 = *(float4*)&As[kk][ty * 8];
            float4 a1 = *(float4*)&As[kk][ty * 8 + 4];
            float4 b  = *(float4*)&Bs[kk][tx * 4];
            float av[8] = {a0.x, a0.y, a0.z, a0.w, a1.x, a1.y, a1.z, a1.w};
            float bvv[4] = {b.x, b.y, b.z, b.w};
#pragma unroll
            for (int i = 0; i < 8; i++)
#pragma unroll
                for (int j = 0; j < 4; j++) acc[i][j] = fmaf(av[i], bvv[j], acc[i][j]);
        }
        __syncthreads();
    }
#pragma unroll
    for (int i = 0; i < 8; i++) {
        int r = row0 + ty * 8 + i;
        float4 o;
        o.x = fmaxf(acc[i][0] + bias[col0 + tx * 4 + 0], 0.0f);
        o.y = fmaxf(acc[i][1] + bias[col0 + tx * 4 + 1], 0.0f);
        o.z = fmaxf(acc[i][2] + bias[col0 + tx * 4 + 2], 0.0f);
        o.w = fmaxf(acc[i][3] + bias[col0 + tx * 4 + 3], 0.0f);
        *(float4*)&C[(size_t)r * N + col0 + tx * 4] = o;
    }
}

// ------ GEMM2 fused: F0 = H @ W2 + b2 ; Fu = rownorm(F0 / dsq) --------------
__global__ __launch_bounds__(256) void gemm2_fused_kernel(const float* __restrict__ A,
                                                          const float* __restrict__ B,
                                                          const float* __restrict__ bias) {
    const int N = OUTD, K = H_DIM;
    __shared__ float As[16][64];
    __shared__ float Bs[16][64];
    int tid = threadIdx.x;
    int tx = tid & 15, ty = tid >> 4;
    int row0 = blockIdx.y * 64;
    int ar = tid >> 2, ak = (tid & 3) * 4;
    int bk = tid >> 4, bc = (tid & 15) * 4;
    const float* Aptr = A + (size_t)(row0 + ar) * K + ak;
    const float* Bptr = B + (size_t)bk * N + bc;

    float acc[4][4];
#pragma unroll
    for (int i = 0; i < 4; i++)
#pragma unroll
        for (int j = 0; j < 4; j++) acc[i][j] = 0.0f;

    float4 av = *(const float4*)Aptr;
    float4 bv = *(const float4*)Bptr;

    for (int k0 = 0; k0 < K; k0 += 16) {
        As[ak + 0][ar] = av.x; As[ak + 1][ar] = av.y;
        As[ak + 2][ar] = av.z; As[ak + 3][ar] = av.w;
        *(float4*)&Bs[bk][bc] = bv;
        __syncthreads();
        if (k0 + 16 < K) {
            av = *(const float4*)(Aptr + k0 + 16);
            bv = *(const float4*)(Bptr + (size_t)(k0 + 16) * N);
        }
#pragma unroll
        for (int kk = 0; kk < 16; kk++) {
            float4 a = *(float4*)&As[kk][ty * 4];
            float4 b = *(float4*)&Bs[kk][tx * 4];
            float avr[4] = {a.x, a.y, a.z, a.w};
            float bvr[4] = {b.x, b.y, b.z, b.w};
#pragma unroll
            for (int i = 0; i < 4; i++)
#pragma unroll
                for (int j = 0; j < 4; j++) acc[i][j] = fmaf(avr[i], bvr[j], acc[i][j]);
        }
        __syncthreads();
    }
    // epilogue: F0 store + fused normalize -> Fu  (row spread over 16 lanes)
#pragma unroll
    for (int i = 0; i < 4; i++) {
        int r = row0 + ty * 4 + i;
        float4 o;
        o.x = acc[i][0] + bias[tx * 4 + 0];
        o.y = acc[i][1] + bias[tx * 4 + 1];
        o.z = acc[i][2] + bias[tx * 4 + 2];
        o.w = acc[i][3] + bias[tx * 4 + 3];
        *(float4*)&g_F0[r * OUTD + tx * 4] = o;
        float d = g_dsq[r];
        float vx = o.x / d, vy = o.y / d, vz = o.z / d, vw = o.w / d;
        float p = vx * vx + vy * vy + vz * vz + vw * vw;
#pragma unroll
        for (int off = 8; off; off >>= 1) p += __shfl_xor_sync(0xffffffffu, p, off);
        float inv = 1.0f / fmaxf(sqrtf(p), EPSV);
        float4 fo;
        fo.x = vx * inv; fo.y = vy * inv; fo.z = vz * inv; fo.w = vw * inv;
        *(float4*)&g_Fu[r * OUTD + tx * 4] = fo;
    }
}

// ---- per-edge y: float4 half-warp dot; WARP-UNIFORM trip count -------------
__global__ __launch_bounds__(256) void ycompute_kernel() {
    __shared__ unsigned hist[256];
    int row = blockIdx.x, tid = threadIdx.x;
    int lane = tid & 31, warp = tid >> 5;
    int half = lane >> 4, hl = lane & 15;       // half-warp id, lane within half
    hist[tid] = 0;
    __syncthreads();
    float4 f4 = *(const float4*)&g_Fu[row * OUTD + hl * 4];
    int cnt = g_cnt[row];
    const int* cols = g_cols + row * MAXDEG;
    float* yrow = g_y + row * MAXDEG;
    // eb is uniform across the warp -> all 32 lanes take every iteration together
    for (int eb = warp * 2; eb < cnt; eb += 16) {
        int e = eb + half;
        bool valid = (e < cnt);
        int j = cols[valid ? e : eb];
        float4 g4 = *(const float4*)&g_Fu[j * OUTD + hl * 4];
        float p = f4.x * g4.x + f4.y * g4.y + f4.z * g4.z + f4.w * g4.w;
        p += __shfl_xor_sync(0xffffffffu, p, 8);
        p += __shfl_xor_sync(0xffffffffu, p, 4);
        p += __shfl_xor_sync(0xffffffffu, p, 2);
        p += __shfl_xor_sync(0xffffffffu, p, 1);
        if (valid && hl == 0) {
            float yv = fminf(fmaxf(1.0f - p, 0.0f), 2.0f);
            yrow[e] = yv;
            atomicAdd(&hist[__float_as_uint(yv) >> 24], 1u);
        }
    }
    __syncthreads();
    if (hist[tid]) atomicAdd(&g_hist0[tid], hist[tid]);
}

// -------- fused exact select: 8-bit level-0 + TWO 12-bit passes -------------
__global__ __launch_bounds__(256) void sel_fused_kernel(const float* __restrict__ lg0,
                                                        const float* __restrict__ rdec,
                                                        const float* __restrict__ ralpha,
                                                        int kiter) {
    __shared__ unsigned h[2][4096];      // 32 KB: per-rank 4096-bin histograms
    __shared__ unsigned sscan[256];
    __shared__ unsigned sprefix[2];
    __shared__ int      srank[2];
    int tid = threadIdx.x;
    int M = g_M;

    float g0 = expf(lg0[0]);
    float rr = 1.0f / (1.0f + expf(-rdec[0]));
    float gp = g0 * powf(rr, (float)kiter);
    float al = 1.0f / (1.0f + expf(-ralpha[0]));

    if (M <= 0) {       // uniform across all blocks: no barrier imbalance
        if (blockIdx.x == 0 && tid == 0) {
            float gd = 1.0f;
            g_lamc = al * (gp / A_SCAD) + (1.0f - al) * (gd / A_SCAD);
        }
        return;
    }

    double idx = 0.75 * (double)(M - 1);
    long k0l = (long)floor(idx);
    float frac = (float)(idx - (double)k0l);
    int R0 = (int)k0l;
    long k1l = k0l + 1; if (k1l > (long)(M - 1)) k1l = M - 1;
    int R1 = (int)k1l;

    // level-0: scan g_hist0 (top byte), locate bins for both ranks (per-block)
    unsigned c = g_hist0[tid];
    sscan[tid] = c;
    __syncthreads();
    for (int off = 1; off < 256; off <<= 1) {
        unsigned v = (tid >= off) ? sscan[tid - off] : 0;
        __syncthreads();
        sscan[tid] += v;
        __syncthreads();
    }
    {
        unsigned incl = sscan[tid], excl = incl - c;
        if ((unsigned)R0 >= excl && (unsigned)R0 < incl) { sprefix[0] = (unsigned)tid << 24; srank[0] = R0 - (int)excl; }
        if ((unsigned)R1 >= excl && (unsigned)R1 < incl) { sprefix[1] = (unsigned)tid << 24; srank[1] = R1 - (int)excl; }
    }
    __syncthreads();
    unsigned p0 = sprefix[0], p1 = sprefix[1];
    int r0 = srank[0], r1 = srank[1];
    __syncthreads();

    // two 12-bit passes: bits [23:12] then [11:0]
    for (int p = 0; p < 2; p++) {
        int sh = (p == 0) ? 12 : 0;
        unsigned hm = (p == 0) ? 0xFF000000u : 0xFFFFF000u;
        for (int i = tid; i < 2 * 4096; i += 256) ((unsigned*)h)[i] = 0;
        __syncthreads();
        const int T = N_NODES * MAXDEG;
        for (int s = blockIdx.x * 256 + tid; s < T; s += SEL_BLOCKS * 256) {
            unsigned u = __float_as_uint(g_y[s]);
            unsigned b = (u >> sh) & 0xFFFu;
            if ((u & hm) == p0) atomicAdd(&h[0][b], 1u);
            if ((u & hm) == p1) atomicAdd(&h[1][b], 1u);
        }
        __syncthreads();
        for (int i = tid; i < 4096; i += 256) {
            if (h[0][i]) atomicAdd(&g_sel12[p][0][i], h[0][i]);
            if (h[1][i]) atomicAdd(&g_sel12[p][1][i], h[1][i]);
        }
        grid_bar(SEL_BLOCKS);
        // each block redundantly scans the completed 4096-bin histograms
        for (int t2 = 0; t2 < 2; t2++) {
            const unsigned* H = g_sel12[p][t2];
            int base = tid * 16;
            unsigned cnts[16];
            unsigned csum = 0;
#pragma unroll
            for (int i2 = 0; i2 < 16; i2++) { cnts[i2] = H[base + i2]; csum += cnts[i2]; }
            sscan[tid] = csum;
            __syncthreads();
            for (int off = 1; off < 256; off <<= 1) {
                unsigned v = (tid >= off) ? sscan[tid - off] : 0;
                __syncthreads();
                sscan[tid] += v;
                __syncthreads();
            }
            unsigned incl = sscan[tid], excl = incl - csum;
            int r = (t2 == 0) ? r0 : r1;
            if ((unsigned)r >= excl && (unsigned)r < incl) {
                unsigned cum = excl;
#pragma unroll
                for (int i2 = 0; i2 < 16; i2++) {
                    if (cum + cnts[i2] > (unsigned)r) {
                        sprefix[t2] = ((t2 == 0) ? p0 : p1) | ((unsigned)(base + i2) << sh);
                        srank[t2] = r - (int)cum;
                        break;
                    }
                    cum += cnts[i2];
                }
            }
            __syncthreads();
        }
        p0 = sprefix[0]; p1 = sprefix[1];
        r0 = srank[0];   r1 = srank[1];
        __syncthreads();
    }
    if (blockIdx.x == 0 && tid == 0) {
        float v0 = __uint_as_float(p0);
        float v1 = __uint_as_float(p1);
        float gd = fmaxf(v0 * (1.0f - frac) + v1 * frac, EPSV);
        g_lamc = al * (gp / A_SCAD) + (1.0f - al) * (gd / A_SCAD);
    }
}

// ------- SCAD weights + sparse propagation (+fused normalize, hist zeroing) --
__global__ __launch_bounds__(64) void propagate_kernel(const float* __restrict__ Fin,
                                                       float* __restrict__ Fout,
                                                       float lam, int write_fu) {
    __shared__ float ssc[MAXDEG];
    __shared__ int   sj[MAXDEG];
    __shared__ float red[2];
    int row = blockIdx.x, t = threadIdx.x;

    // zero histograms for next iteration (rows 0..262 cover 256 + 16384 words)
    {
        int gid = row * 64 + t;
        if (gid < 256) g_hist0[gid] = 0;
        else if (gid < 256 + SEL12_WORDS) ((unsigned*)g_sel12)[gid - 256] = 0;
    }

    int cnt = g_cnt[row];
    float lamc = g_lamc;
    float di  = g_dsq[row];
    float rdi = g_rdsq[row];
    float ps = 0.0f;
    for (int e = t; e < cnt; e += 64) {
        float y  = g_y[row * MAXDEG + e];
        float ys = fmaxf(y, EPSV);
        float wm = (A_SCAD * lamc - y) / ((A_SCAD - 1.0f) * ys);
        float w  = (y <= lamc) ? 1.0f : ((y <= A_SCAD * lamc) ? wm : 0.0f);
        int j = g_cols[row * MAXDEG + e];
        ssc[e] = w * rdi * g_rdsq[j];      // W * A_tilde at the edge (no division)
        sj[e]  = j;
        ps += w;
    }
#pragma unroll
    for (int o = 16; o; o >>= 1) ps += __shfl_xor_sync(0xffffffffu, ps, o);
    if ((t & 31) == 0) red[t >> 5] = ps;
    __syncthreads();
    float S = red[0] + red[1];
    float Q = S / (float)(cnt + 1) + lam;
    // 4-accumulator gather (MLP)
    float a0 = 0.0f, a1 = 0.0f, a2 = 0.0f, a3 = 0.0f;
    int e = 0;
    for (; e + 4 <= cnt; e += 4) {
        a0 = fmaf(ssc[e + 0], Fin[sj[e + 0] * OUTD + t], a0);
        a1 = fmaf(ssc[e + 1], Fin[sj[e + 1] * OUTD + t], a1);
        a2 = fmaf(ssc[e + 2], Fin[sj[e + 2] * OUTD + t], a2);
        a3 = fmaf(ssc[e + 3], Fin[sj[e + 3] * OUTD + t], a3);
    }
    for (; e < cnt; e++) a0 = fmaf(ssc[e], Fin[sj[e] * OUTD + t], a0);
    float acc = (a0 + a1) + (a2 + a3);
    float f0 = g_F0[row * OUTD + t];
    float outv = acc / Q + lam * f0 / Q;
    Fout[row * OUTD + t] = outv;

    if (write_fu) {
        float v = outv / di;
        float s2 = v * v;
#pragma unroll
        for (int o = 16; o; o >>= 1) s2 += __shfl_xor_sync(0xffffffffu, s2, o);
        __shared__ float red2[2];
        if ((t & 31) == 0) red2[t >> 5] = s2;
        __syncthreads();
        float nrm = sqrtf(red2[0] + red2[1]);
        g_Fu[row * OUTD + t] = v / fmaxf(nrm, EPSV);
    }
}

// ---------------- host launcher ---------------------------------------------
extern "C" void kernel_launch(void* const* d_in, const int* in_sizes, int n_in,
                              void* d_out, int out_size) {
    const float* A      = (const float*)d_in[0];
    const float* X      = (const float*)d_in[1];
    const float* W1     = (const float*)d_in[2];
    const float* b1     = (const float*)d_in[3];
    const float* W2     = (const float*)d_in[4];
    const float* b2     = (const float*)d_in[5];
    const float* lg0    = (const float*)d_in[6];
    const float* rdec   = (const float*)d_in[7];
    const float* ralpha = (const float*)d_in[8];
    float* out = (float*)d_out;

    // DEVICE addresses of the __device__ buffers (host shadow symbols are NOT valid!)
    float *pH, *pF0, *pFA, *pFB;
    cudaGetSymbolAddress((void**)&pH,  g_H);
    cudaGetSymbolAddress((void**)&pF0, g_F0);
    cudaGetSymbolAddress((void**)&pFA, g_FA);
    cudaGetSymbolAddress((void**)&pFB, g_FB);

    // fork: reset+build (reads A) runs concurrently with gemm1 (reads X,W1)
    cudaEventRecord(g_evFork, 0);
    cudaStreamWaitEvent(g_s2, g_evFork, 0);
    reset_kernel<<<1, 1024, 0, g_s2>>>();
    build_kernel<<<N_NODES, 256, 0, g_s2>>>(A);
    cudaEventRecord(g_evJoin, g_s2);

    gemm1_kernel<<<dim3(H_DIM / 64, N_NODES / 128), 256>>>(X, W1, b1, pH);
    // gemm2's normalize epilogue needs g_dsq from build: join before gemm2
    cudaStreamWaitEvent(0, g_evJoin, 0);
    gemm2_fused_kernel<<<dim3(1, N_NODES / 64), 256>>>(pH, W2, b2);

    for (int k = 0; k < PROP_STEP; k++) {
        const float* Fin = (k == 0) ? pF0 : ((k & 1) ? pFA : pFB);
        float* Fout = (k == PROP_STEP - 1) ? out : ((k & 1) ? pFB : pFA);

        ycompute_kernel<<<N_NODES, 256>>>();
        sel_fused_kernel<<<SEL_BLOCKS, 256>>>(lg0, rdec, ralpha, k);
        propagate_kernel<<<N_NODES, 64>>>(Fin, Fout, LAMF, (k < PROP_STEP - 1) ? 1 : 0);
    }
}

// round 15
// speedup vs baseline: 1.5538x; 1.0141x over previous
#include <cuda_runtime.h>
#include <math.h>

// Problem constants (fixed by setup_inputs)
#define N_NODES 4096
#define IN_DIM  512
#define H_DIM   256
#define OUTD    64
#define MAXDEG  192
#define EPSV    1e-8f
#define A_SCAD  3.7f
#define PROP_STEP 4
#define SEL_BLOCKS 148        // <= SM count: all blocks co-resident -> spin barrier is safe

static const float LAMF = (float)(1.0 / 0.9 - 1.0);   // 1/LAM_HAT - 1

// ---------------- device scratch (static, no allocation) ----------------
__device__ float g_dsq [N_NODES];
__device__ float g_rdsq[N_NODES];
__device__ int   g_cnt[N_NODES];
__device__ int   g_cols[N_NODES * MAXDEG];
__device__ float g_y   [N_NODES * MAXDEG];
__device__ float g_Fu  [N_NODES * OUTD];
__device__ float g_F0  [N_NODES * OUTD];
__device__ float g_FA  [N_NODES * OUTD];
__device__ float g_FB  [N_NODES * OUTD];
__device__ float g_H   [N_NODES * H_DIM];
__device__ unsigned g_hist0[256];
__device__ unsigned g_sel12[2][2][4096];   // [pass][rank][bin] per-pass buffers
__device__ float    g_lamc;
__device__ int      g_M;
__device__ int          g_bar_count;
__device__ volatile int g_bar_phase;

#define SEL12_WORDS (2 * 2 * 4096)

// ---------------- stream fork resources (created at load, never in capture) --
static cudaStream_t g_s2;
static cudaEvent_t  g_evFork, g_evJoin;
namespace {
struct StreamInit {
    StreamInit() {
        cudaStreamCreateWithFlags(&g_s2, cudaStreamNonBlocking);
        cudaEventCreateWithFlags(&g_evFork, cudaEventDisableTiming);
        cudaEventCreateWithFlags(&g_evJoin, cudaEventDisableTiming);
    }
};
StreamInit g_stream_init;
}

// ---------------- grid barrier (requires all blocks co-resident) ------------
__device__ __forceinline__ void grid_bar(int nb) {
    __syncthreads();
    if (threadIdx.x == 0) {
        __threadfence();
        int gen = g_bar_phase;
        if (atomicAdd(&g_bar_count, 1) == nb - 1) {
            g_bar_count = 0;
            __threadfence();
            g_bar_phase = gen + 1;
        } else {
            while (g_bar_phase == gen) __nanosleep(64);
        }
        __threadfence();
    }
    __syncthreads();
}

// ---------------- reset ----------------
__global__ void reset_kernel() {
    int i = threadIdx.x;
    if (i == 0) { g_M = 0; g_bar_count = 0; g_bar_phase = 0; }
    if (i < 256) g_hist0[i] = 0;
    for (int j = i; j < SEL12_WORDS; j += blockDim.x) ((unsigned*)g_sel12)[j] = 0;
}

// ---------------- build padded adjacency (deterministic, column-sorted) ----
__global__ __launch_bounds__(256) void build_kernel(const float* __restrict__ A) {
    __shared__ unsigned char sbit[N_NODES];
    __shared__ int scnt[256];
    int row = blockIdx.x, tid = threadIdx.x;
    const float* Arow = A + (size_t)row * N_NODES;
    for (int i = tid; i < N_NODES; i += 256) sbit[i] = (Arow[i] != 0.0f);
    __syncthreads();
    int c0 = tid * 16;
    int cnt = 0;
#pragma unroll
    for (int c = 0; c < 16; c++) cnt += sbit[c0 + c];
    scnt[tid] = cnt;
    __syncthreads();
    for (int off = 1; off < 256; off <<= 1) {
        int v = (tid >= off) ? scnt[tid - off] : 0;
        __syncthreads();
        scnt[tid] += v;
        __syncthreads();
    }
    int base  = scnt[tid] - cnt;
    int total = scnt[255];
    int pos = base;
    for (int c = 0; c < 16; c++)
        if (sbit[c0 + c] && pos < MAXDEG) g_cols[row * MAXDEG + (pos++)] = c0 + c;
    int t = min(total, MAXDEG);
    // one-time +inf padding of g_y (never rewritten; sorts past all real y)
    for (int e = t + tid; e < MAXDEG; e += 256)
        g_y[row * MAXDEG + e] = __int_as_float(0x7f800000);
    if (tid == 0) {
        g_cnt[row] = t;
        float d = sqrtf((float)(total + 1));   // D = deg + self-loop
        g_dsq[row]  = d;
        g_rdsq[row] = 1.0f / d;
        atomicAdd(&g_M, t);
    }
}

// ---- GEMM1: H = relu(X @ W1 + b1). 128x64 tile, double-buffered smem -------
__global__ __launch_bounds__(256) void gemm1_kernel(const float* __restrict__ A,
                                                    const float* __restrict__ B,
                                                    const float* __restrict__ bias,
                                                    float* __restrict__ C) {
    const int N = H_DIM, K = IN_DIM;
    __shared__ float As[2][16][128];
    __shared__ float Bs[2][16][64];
    int tid = threadIdx.x;
    int tx = tid & 15, ty = tid >> 4;
    int row0 = blockIdx.y * 128, col0 = blockIdx.x * 64;
    int ar = tid >> 1, ak = (tid & 1) * 8;
    int bk = tid >> 4, bc = (tid & 15) * 4;
    const float* Aptr = A + (size_t)(row0 + ar) * K + ak;
    const float* Bptr = B + (size_t)bk * N + col0 + bc;

    float acc[8][4];
#pragma unroll
    for (int i = 0; i < 8; i++)
#pragma unroll
        for (int j = 0; j < 4; j++) acc[i][j] = 0.0f;

    float4 av0 = *(const float4*)Aptr;
    float4 av1 = *(const float4*)(Aptr + 4);
    float4 bv  = *(const float4*)Bptr;
    As[0][ak + 0][ar] = av0.x; As[0][ak + 1][ar] = av0.y;
    As[0][ak + 2][ar] = av0.z; As[0][ak + 3][ar] = av0.w;
    As[0][ak + 4][ar] = av1.x; As[0][ak + 5][ar] = av1.y;
    As[0][ak + 6][ar] = av1.z; As[0][ak + 7][ar] = av1.w;
    *(float4*)&Bs[0][bk][bc] = bv;
    __syncthreads();

    int buf = 0;
    for (int k0 = 16;; k0 += 16) {
        bool have_next = (k0 < K);
        if (have_next) {
            av0 = *(const float4*)(Aptr + k0);
            av1 = *(const float4*)(Aptr + k0 + 4);
            bv  = *(const float4*)(Bptr + (size_t)k0 * N);
        }
#pragma unroll
        for (int kk = 0; kk < 16; kk++) {
            float4 a0 = *(float4*)&As[buf][kk][ty * 8];
            float4 a1 = *(float4*)&As[buf][kk][ty * 8 + 4];
            float4 b  = *(float4*)&Bs[buf][kk][tx * 4];
            float av[8] = {a0.x, a0.y, a0.z, a0.w, a1.x, a1.y, a1.z, a1.w};
            float bvv[4] = {b.x, b.y, b.z, b.w};
#pragma unroll
            for (int i = 0; i < 8; i++)
#pragma unroll
                for (int j = 0; j < 4; j++) acc[i][j] = fmaf(av[i], bvv[j], acc[i][j]);
        }
        if (!have_next) break;
        int nb = buf ^ 1;
        As[nb][ak + 0][ar] = av0.x; As[nb][ak + 1][ar] = av0.y;
        As[nb][ak + 2][ar] = av0.z; As[nb][ak + 3][ar] = av0.w;
        As[nb][ak + 4][ar] = av1.x; As[nb][ak + 5][ar] = av1.y;
        As[nb][ak + 6][ar] = av1.z; As[nb][ak + 7][ar] = av1.w;
        *(float4*)&Bs[nb][bk][bc] = bv;
        __syncthreads();
        buf = nb;
    }
#pragma unroll
    for (int i = 0; i < 8; i++) {
        int r = row0 + ty * 8 + i;
        float4 o;
        o.x = fmaxf(acc[i][0] + bias[col0 + tx * 4 + 0], 0.0f);
        o.y = fmaxf(acc[i][1] + bias[col0 + tx * 4 + 1], 0.0f);
        o.z = fmaxf(acc[i][2] + bias[col0 + tx * 4 + 2], 0.0f);
        o.w = fmaxf(acc[i][3] + bias[col0 + tx * 4 + 3], 0.0f);
        *(float4*)&C[(size_t)r * N + col0 + tx * 4] = o;
    }
}

// ------ GEMM2 fused (double-buffered): F0 = H @ W2 + b2 ; Fu = rownorm ------
__global__ __launch_bounds__(256) void gemm2_fused_kernel(const float* __restrict__ A,
                                                          const float* __restrict__ B,
                                                          const float* __restrict__ bias) {
    const int N = OUTD, K = H_DIM;
    __shared__ float As[2][16][64];
    __shared__ float Bs[2][16][64];
    int tid = threadIdx.x;
    int tx = tid & 15, ty = tid >> 4;
    int row0 = blockIdx.y * 64;
    int ar = tid >> 2, ak = (tid & 3) * 4;
    int bk = tid >> 4, bc = (tid & 15) * 4;
    const float* Aptr = A + (size_t)(row0 + ar) * K + ak;
    const float* Bptr = B + (size_t)bk * N + bc;

    float acc[4][4];
#pragma unroll
    for (int i = 0; i < 4; i++)
#pragma unroll
        for (int j = 0; j < 4; j++) acc[i][j] = 0.0f;

    float4 av = *(const float4*)Aptr;
    float4 bv = *(const float4*)Bptr;
    As[0][ak + 0][ar] = av.x; As[0][ak + 1][ar] = av.y;
    As[0][ak + 2][ar] = av.z; As[0][ak + 3][ar] = av.w;
    *(float4*)&Bs[0][bk][bc] = bv;
    __syncthreads();

    int buf = 0;
    for (int k0 = 16;; k0 += 16) {
        bool have_next = (k0 < K);
        if (have_next) {
            av = *(const float4*)(Aptr + k0);
            bv = *(const float4*)(Bptr + (size_t)k0 * N);
        }
#pragma unroll
        for (int kk = 0; kk < 16; kk++) {
            float4 a = *(float4*)&As[buf][kk][ty * 4];
            float4 b = *(float4*)&Bs[buf][kk][tx * 4];
            float avr[4] = {a.x, a.y, a.z, a.w};
            float bvr[4] = {b.x, b.y, b.z, b.w};
#pragma unroll
            for (int i = 0; i < 4; i++)
#pragma unroll
                for (int j = 0; j < 4; j++) acc[i][j] = fmaf(avr[i], bvr[j], acc[i][j]);
        }
        if (!have_next) break;
        int nb = buf ^ 1;
        As[nb][ak + 0][ar] = av.x; As[nb][ak + 1][ar] = av.y;
        As[nb][ak + 2][ar] = av.z; As[nb][ak + 3][ar] = av.w;
        *(float4*)&Bs[nb][bk][bc] = bv;
        __syncthreads();
        buf = nb;
    }
    // epilogue: F0 store + fused normalize -> Fu  (row spread over 16 lanes)
#pragma unroll
    for (int i = 0; i < 4; i++) {
        int r = row0 + ty * 4 + i;
        float4 o;
        o.x = acc[i][0] + bias[tx * 4 + 0];
        o.y = acc[i][1] + bias[tx * 4 + 1];
        o.z = acc[i][2] + bias[tx * 4 + 2];
        o.w = acc[i][3] + bias[tx * 4 + 3];
        *(float4*)&g_F0[r * OUTD + tx * 4] = o;
        float d = g_dsq[r];
        float vx = o.x / d, vy = o.y / d, vz = o.z / d, vw = o.w / d;
        float p = vx * vx + vy * vy + vz * vz + vw * vw;
#pragma unroll
        for (int off = 8; off; off >>= 1) p += __shfl_xor_sync(0xffffffffu, p, off);
        float inv = 1.0f / fmaxf(sqrtf(p), EPSV);
        float4 fo;
        fo.x = vx * inv; fo.y = vy * inv; fo.z = vz * inv; fo.w = vw * inv;
        *(float4*)&g_Fu[r * OUTD + tx * 4] = fo;
    }
}

// ---- per-edge y: float4 half-warp dot; WARP-UNIFORM trip count -------------
__global__ __launch_bounds__(256) void ycompute_kernel() {
    __shared__ unsigned hist[256];
    int row = blockIdx.x, tid = threadIdx.x;
    int lane = tid & 31, warp = tid >> 5;
    int half = lane >> 4, hl = lane & 15;       // half-warp id, lane within half
    hist[tid] = 0;
    __syncthreads();
    float4 f4 = *(const float4*)&g_Fu[row * OUTD + hl * 4];
    int cnt = g_cnt[row];
    const int* cols = g_cols + row * MAXDEG;
    float* yrow = g_y + row * MAXDEG;
    // eb is uniform across the warp -> all 32 lanes take every iteration together
    for (int eb = warp * 2; eb < cnt; eb += 16) {
        int e = eb + half;
        bool valid = (e < cnt);
        int j = cols[valid ? e : eb];
        float4 g4 = *(const float4*)&g_Fu[j * OUTD + hl * 4];
        float p = f4.x * g4.x + f4.y * g4.y + f4.z * g4.z + f4.w * g4.w;
        p += __shfl_xor_sync(0xffffffffu, p, 8);
        p += __shfl_xor_sync(0xffffffffu, p, 4);
        p += __shfl_xor_sync(0xffffffffu, p, 2);
        p += __shfl_xor_sync(0xffffffffu, p, 1);
        if (valid && hl == 0) {
            float yv = fminf(fmaxf(1.0f - p, 0.0f), 2.0f);
            yrow[e] = yv;
            atomicAdd(&hist[__float_as_uint(yv) >> 24], 1u);
        }
    }
    __syncthreads();
    if (hist[tid]) atomicAdd(&g_hist0[tid], hist[tid]);
}

// -------- fused exact select: 8-bit level-0 + TWO 12-bit passes (uint4) -----
__global__ __launch_bounds__(256) void sel_fused_kernel(const float* __restrict__ lg0,
                                                        const float* __restrict__ rdec,
                                                        const float* __restrict__ ralpha,
                                                        int kiter) {
    __shared__ unsigned h[2][4096];      // 32 KB: per-rank 4096-bin histograms
    __shared__ unsigned sscan[256];
    __shared__ unsigned sprefix[2];
    __shared__ int      srank[2];
    int tid = threadIdx.x;
    int M = g_M;

    float g0 = expf(lg0[0]);
    float rr = 1.0f / (1.0f + expf(-rdec[0]));
    float gp = g0 * powf(rr, (float)kiter);
    float al = 1.0f / (1.0f + expf(-ralpha[0]));

    if (M <= 0) {       // uniform across all blocks: no barrier imbalance
        if (blockIdx.x == 0 && tid == 0) {
            float gd = 1.0f;
            g_lamc = al * (gp / A_SCAD) + (1.0f - al) * (gd / A_SCAD);
        }
        return;
    }

    double idx = 0.75 * (double)(M - 1);
    long k0l = (long)floor(idx);
    float frac = (float)(idx - (double)k0l);
    int R0 = (int)k0l;
    long k1l = k0l + 1; if (k1l > (long)(M - 1)) k1l = M - 1;
    int R1 = (int)k1l;

    // level-0: scan g_hist0 (top byte), locate bins for both ranks (per-block)
    unsigned c = g_hist0[tid];
    sscan[tid] = c;
    __syncthreads();
    for (int off = 1; off < 256; off <<= 1) {
        unsigned v = (tid >= off) ? sscan[tid - off] : 0;
        __syncthreads();
        sscan[tid] += v;
        __syncthreads();
    }
    {
        unsigned incl = sscan[tid], excl = incl - c;
        if ((unsigned)R0 >= excl && (unsigned)R0 < incl) { sprefix[0] = (unsigned)tid << 24; srank[0] = R0 - (int)excl; }
        if ((unsigned)R1 >= excl && (unsigned)R1 < incl) { sprefix[1] = (unsigned)tid << 24; srank[1] = R1 - (int)excl; }
    }
    __syncthreads();
    unsigned p0 = sprefix[0], p1 = sprefix[1];
    int r0 = srank[0], r1 = srank[1];
    __syncthreads();

    // two 12-bit passes: bits [23:12] then [11:0], uint4-vectorized reads
    const uint4* y4 = (const uint4*)g_y;
    const int T4 = (N_NODES * MAXDEG) / 4;
    for (int p = 0; p < 2; p++) {
        int sh = (p == 0) ? 12 : 0;
        unsigned hm = (p == 0) ? 0xFF000000u : 0xFFFFF000u;
        for (int i = tid; i < 2 * 4096; i += 256) ((unsigned*)h)[i] = 0;
        __syncthreads();
        for (int s = blockIdx.x * 256 + tid; s < T4; s += SEL_BLOCKS * 256) {
            uint4 u4 = y4[s];
            unsigned uu[4] = {u4.x, u4.y, u4.z, u4.w};
#pragma unroll
            for (int q = 0; q < 4; q++) {
                unsigned u = uu[q];
                unsigned b = (u >> sh) & 0xFFFu;
                if ((u & hm) == p0) atomicAdd(&h[0][b], 1u);
                if ((u & hm) == p1) atomicAdd(&h[1][b], 1u);
            }
        }
        __syncthreads();
        for (int i = tid; i < 4096; i += 256) {
            if (h[0][i]) atomicAdd(&g_sel12[p][0][i], h[0][i]);
            if (h[1][i]) atomicAdd(&g_sel12[p][1][i], h[1][i]);
        }
        grid_bar(SEL_BLOCKS);
        // each block redundantly scans the completed 4096-bin histograms
        for (int t2 = 0; t2 < 2; t2++) {
            const unsigned* H = g_sel12[p][t2];
            int base = tid * 16;
            unsigned cnts[16];
            unsigned csum = 0;
#pragma unroll
            for (int i2 = 0; i2 < 16; i2++) { cnts[i2] = H[base + i2]; csum += cnts[i2]; }
            sscan[tid] = csum;
            __syncthreads();
            for (int off = 1; off < 256; off <<= 1) {
                unsigned v = (tid >= off) ? sscan[tid - off] : 0;
                __syncthreads();
                sscan[tid] += v;
                __syncthreads();
            }
            unsigned incl = sscan[tid], excl = incl - csum;
            int r = (t2 == 0) ? r0 : r1;
            if ((unsigned)r >= excl && (unsigned)r < incl) {
                unsigned cum = excl;
#pragma unroll
                for (int i2 = 0; i2 < 16; i2++) {
                    if (cum + cnts[i2] > (unsigned)r) {
                        sprefix[t2] = ((t2 == 0) ? p0 : p1) | ((unsigned)(base + i2) << sh);
                        srank[t2] = r - (int)cum;
                        break;
                    }
                    cum += cnts[i2];
                }
            }
            __syncthreads();
        }
        p0 = sprefix[0]; p1 = sprefix[1];
        r0 = srank[0];   r1 = srank[1];
        __syncthreads();
    }
    if (blockIdx.x == 0 && tid == 0) {
        float v0 = __uint_as_float(p0);
        float v1 = __uint_as_float(p1);
        float gd = fmaxf(v0 * (1.0f - frac) + v1 * frac, EPSV);
        g_lamc = al * (gp / A_SCAD) + (1.0f - al) * (gd / A_SCAD);
    }
}

// ------- SCAD weights + sparse propagation (+fused normalize, hist zeroing) --
__global__ __launch_bounds__(64) void propagate_kernel(const float* __restrict__ Fin,
                                                       float* __restrict__ Fout,
                                                       float lam, int write_fu) {
    __shared__ float ssc[MAXDEG];
    __shared__ int   sj[MAXDEG];
    __shared__ float red[2];
    int row = blockIdx.x, t = threadIdx.x;

    // zero histograms for next iteration (rows 0..262 cover 256 + 16384 words)
    {
        int gid = row * 64 + t;
        if (gid < 256) g_hist0[gid] = 0;
        else if (gid < 256 + SEL12_WORDS) ((unsigned*)g_sel12)[gid - 256] = 0;
    }

    int cnt = g_cnt[row];
    float lamc = g_lamc;
    float di  = g_dsq[row];
    float rdi = g_rdsq[row];
    float ps = 0.0f;
    for (int e = t; e < cnt; e += 64) {
        float y  = g_y[row * MAXDEG + e];
        float ys = fmaxf(y, EPSV);
        float wm = (A_SCAD * lamc - y) / ((A_SCAD - 1.0f) * ys);
        float w  = (y <= lamc) ? 1.0f : ((y <= A_SCAD * lamc) ? wm : 0.0f);
        int j = g_cols[row * MAXDEG + e];
        ssc[e] = w * rdi * g_rdsq[j];      // W * A_tilde at the edge (no division)
        sj[e]  = j;
        ps += w;
    }
#pragma unroll
    for (int o = 16; o; o >>= 1) ps += __shfl_xor_sync(0xffffffffu, ps, o);
    if ((t & 31) == 0) red[t >> 5] = ps;
    __syncthreads();
    float S = red[0] + red[1];
    float Q = S / (float)(cnt + 1) + lam;
    // 4-accumulator gather (MLP)
    float a0 = 0.0f, a1 = 0.0f, a2 = 0.0f, a3 = 0.0f;
    int e = 0;
    for (; e + 4 <= cnt; e += 4) {
        a0 = fmaf(ssc[e + 0], Fin[sj[e + 0] * OUTD + t], a0);
        a1 = fmaf(ssc[e + 1], Fin[sj[e + 1] * OUTD + t], a1);
        a2 = fmaf(ssc[e + 2], Fin[sj[e + 2] * OUTD + t], a2);
        a3 = fmaf(ssc[e + 3], Fin[sj[e + 3] * OUTD + t], a3);
    }
    for (; e < cnt; e++) a0 = fmaf(ssc[e], Fin[sj[e] * OUTD + t], a0);
    float acc = (a0 + a1) + (a2 + a3);
    float f0 = g_F0[row * OUTD + t];
    float outv = acc / Q + lam * f0 / Q;
    Fout[row * OUTD + t] = outv;

    if (write_fu) {
        float v = outv / di;
        float s2 = v * v;
#pragma unroll
        for (int o = 16; o; o >>= 1) s2 += __shfl_xor_sync(0xffffffffu, s2, o);
        __shared__ float red2[2];
        if ((t & 31) == 0) red2[t >> 5] = s2;
        __syncthreads();
        float nrm = sqrtf(red2[0] + red2[1]);
        g_Fu[row * OUTD + t] = v / fmaxf(nrm, EPSV);
    }
}

// ---------------- host launcher ---------------------------------------------
extern "C" void kernel_launch(void* const* d_in, const int* in_sizes, int n_in,
                              void* d_out, int out_size) {
    const float* A      = (const float*)d_in[0];
    const float* X      = (const float*)d_in[1];
    const float* W1     = (const float*)d_in[2];
    const float* b1     = (const float*)d_in[3];
    const float* W2     = (const float*)d_in[4];
    const float* b2     = (const float*)d_in[5];
    const float* lg0    = (const float*)d_in[6];
    const float* rdec   = (const float*)d_in[7];
    const float* ralpha = (const float*)d_in[8];
    float* out = (float*)d_out;

    // DEVICE addresses of the __device__ buffers (host shadow symbols are NOT valid!)
    float *pH, *pF0, *pFA, *pFB;
    cudaGetSymbolAddress((void**)&pH,  g_H);
    cudaGetSymbolAddress((void**)&pF0, g_F0);
    cudaGetSymbolAddress((void**)&pFA, g_FA);
    cudaGetSymbolAddress((void**)&pFB, g_FB);

    // fork: reset+build (reads A) runs concurrently with gemm1 (reads X,W1)
    cudaEventRecord(g_evFork, 0);
    cudaStreamWaitEvent(g_s2, g_evFork, 0);
    reset_kernel<<<1, 1024, 0, g_s2>>>();
    build_kernel<<<N_NODES, 256, 0, g_s2>>>(A);
    cudaEventRecord(g_evJoin, g_s2);

    gemm1_kernel<<<dim3(H_DIM / 64, N_NODES / 128), 256>>>(X, W1, b1, pH);
    // gemm2's normalize epilogue needs g_dsq from build: join before gemm2
    cudaStreamWaitEvent(0, g_evJoin, 0);
    gemm2_fused_kernel<<<dim3(1, N_NODES / 64), 256>>>(pH, W2, b2);

    for (int k = 0; k < PROP_STEP; k++) {
        const float* Fin = (k == 0) ? pF0 : ((k & 1) ? pFA : pFB);
        float* Fout = (k == PROP_STEP - 1) ? out : ((k & 1) ? pFB : pFA);

        ycompute_kernel<<<N_NODES, 256>>>();
        sel_fused_kernel<<<SEL_BLOCKS, 256>>>(lg0, rdec, ralpha, k);
        propagate_kernel<<<N_NODES, 64>>>(Fin, Fout, LAMF, (k < PROP_STEP - 1) ? 1 : 0);
    }
}